// round 11
// baseline (speedup 1.0000x reference)
#include <cuda_runtime.h>

// SoftmaxProbs: mean = (1/B) * sum_{b,c} l[b,c] * (lse_b - x[b,c])
// 2M rows x 18 classes fp32, HBM-bound (288 MB).
// Warp-owned cp.async double-buffered x staging; phase 1 computes LSE per row
// and WRITES BACK (lse - x) into smem, so phase 2 is a pure float4 dot with
// gmem-streamed labels (batched LDG.128, MLP 4-5). Uniform main region
// (grid*13 chunks) + fine-grained 16-row tail slices for load balance.

#define NC 18
#define BLK 256
#define NWARP (BLK / 32)
#define RPW 32                        // rows per warp per main chunk
#define WF  (RPW * NC)                // 576 floats
#define WV4 (WF / 4)                  // 144 float4
#define TRPW 16                       // tail slice rows
#define MAX_GRID 2048

__device__ double       g_partials[MAX_GRID];
__device__ unsigned int g_count = 0;

__device__ __forceinline__ void cpa16(unsigned int saddr, const float4* g) {
    asm volatile("cp.async.cg.shared.global [%0], [%1], 16;" :: "r"(saddr), "l"(g));
}
__device__ __forceinline__ void cpa_commit() {
    asm volatile("cp.async.commit_group;");
}

__global__ __launch_bounds__(BLK, 4)
void ce_main_kernel(const float* __restrict__ x,
                    const float* __restrict__ lab,
                    float* __restrict__ out,
                    int B, int nchunks_main)
{
    __shared__ float  sx[2][NWARP][WF];     // 36864 B
    __shared__ double sred[NWARP];
    __shared__ int    s_last;

    const int tid  = threadIdx.x;
    const int w    = tid >> 5;
    const int lane = tid & 31;

    auto stage_w = [&](int c, int s) {      // stage this warp's 32-row slice
        const long long r0 = (long long)c * BLK + (long long)w * RPW;
        long long rem = (long long)B - r0;
        if (rem <= 0) return;
        const int wr = rem < RPW ? (int)rem : RPW;
        const float* xb = x + r0 * NC;
        if (wr == RPW) {
            const float4* xb4 = (const float4*)xb;
            const unsigned sxa = (unsigned)__cvta_generic_to_shared(&sx[s][w][0]);
            #pragma unroll
            for (int j = 0; j < 4; j++)
                cpa16(sxa + (lane + j * 32) * 16, xb4 + lane + j * 32);
            if (lane < WV4 - 128)
                cpa16(sxa + (lane + 128) * 16, xb4 + lane + 128);
        } else {
            const int nf = wr * NC;
            for (int i = lane; i < nf; i += 32) sx[s][w][i] = xb[i];
        }
    };

    // Phase 1 for a slice: per-row LSE, write back (lse - x). rows <= 32.
    auto lse_writeback = [&](float* sxw, int wr) {
        if (lane < wr) {
            const float* rx = sxw + lane * NC;
            float xr[NC];
            #pragma unroll
            for (int k = 0; k < NC; k++) xr[k] = rx[k];
            float m = xr[0];
            #pragma unroll
            for (int k = 1; k < NC; k++) m = fmaxf(m, xr[k]);
            float s = 0.f;
            #pragma unroll
            for (int k = 0; k < NC; k++) s += __expf(xr[k] - m);
            const float lse = m + __logf(s);
            float2* wb = (float2*)(sxw + lane * NC);   // 8B aligned (lane*72)
            #pragma unroll
            for (int k = 0; k < NC / 2; k++)
                wb[k] = make_float2(lse - xr[2 * k], lse - xr[2 * k + 1]);
        }
        __syncwarp();
    };

    const int c0 = blockIdx.x;
    double acc = 0.0;

    if (c0 < nchunks_main) stage_w(c0, 0);
    cpa_commit();

    int stg = 0;
    for (int c = c0; c < nchunks_main; c += gridDim.x, stg ^= 1) {
        const int nxt = c + gridDim.x;
        if (nxt < nchunks_main) stage_w(nxt, stg ^ 1);
        cpa_commit();
        asm volatile("cp.async.wait_group 1;");   // this warp's slice of c resident
        __syncwarp();

        const long long r0 = (long long)c * BLK + (long long)w * RPW;
        long long rem = (long long)B - r0;
        const int wr = rem <= 0 ? 0 : (rem < RPW ? (int)rem : RPW);

        float* sxw = &sx[stg][w][0];
        lse_writeback(sxw, wr);                   // sx now holds (lse - x)

        // Phase 2: labels via batched LDG.128; pure dot with smem
        float f0 = 0.f, f1 = 0.f, f2 = 0.f, f3 = 0.f;
        const float* lb = lab + r0 * NC;
        const float4* sxv = (const float4*)sxw;

        if (wr == RPW) {
            const float4* lb4 = (const float4*)lb;
            float4 L0 = lb4[lane      ];
            float4 L1 = lb4[lane +  32];
            float4 L2 = lb4[lane +  64];
            float4 L3 = lb4[lane +  96];
            float4 L4;
            const bool has5 = lane < (WV4 - 128);
            if (has5) L4 = lb4[lane + 128];

            float4 X;
            X = sxv[lane      ]; f0 += L0.x*X.x; f1 += L0.y*X.y; f2 += L0.z*X.z; f3 += L0.w*X.w;
            X = sxv[lane +  32]; f0 += L1.x*X.x; f1 += L1.y*X.y; f2 += L1.z*X.z; f3 += L1.w*X.w;
            X = sxv[lane +  64]; f0 += L2.x*X.x; f1 += L2.y*X.y; f2 += L2.z*X.z; f3 += L2.w*X.w;
            X = sxv[lane +  96]; f0 += L3.x*X.x; f1 += L3.y*X.y; f2 += L3.z*X.z; f3 += L3.w*X.w;
            if (has5) { X = sxv[lane + 128]; f0 += L4.x*X.x; f1 += L4.y*X.y; f2 += L4.z*X.z; f3 += L4.w*X.w; }
        } else if (wr > 0) {
            const int nf = wr * NC;
            for (int i = lane; i < nf; i += 32)
                f0 += lb[i] * sxw[i];
        }
        acc += (double)((f0 + f1) + (f2 + f3));
        __syncwarp();                             // slice reusable for restage
    }
    asm volatile("cp.async.wait_group 0;");
    __syncwarp();

    // ── Fine-grained tail: 16-row slices over all warps (static, balanced) ──
    {
        const long long tail_row0 = (long long)nchunks_main * BLK;
        const long long tailrows  = (long long)B - tail_row0;
        if (tailrows > 0) {
            const int ntslices = (int)((tailrows + TRPW - 1) / TRPW);
            const int GW = gridDim.x * NWARP;
            float* sxw = &sx[0][w][0];
            for (int ts = blockIdx.x * NWARP + w; ts < ntslices; ts += GW) {
                const long long r0 = tail_row0 + (long long)ts * TRPW;
                long long rem = (long long)B - r0;
                const int wr = rem < TRPW ? (int)rem : TRPW;
                const float* xb = x + r0 * NC;      // 16B aligned (1152B slices)
                if (wr == TRPW) {
                    const float4* xb4 = (const float4*)xb;
                    const unsigned sxa = (unsigned)__cvta_generic_to_shared(sxw);
                    cpa16(sxa + lane * 16,        xb4 + lane);
                    cpa16(sxa + (lane + 32) * 16, xb4 + lane + 32);
                    if (lane < 8) cpa16(sxa + (lane + 64) * 16, xb4 + lane + 64);
                    cpa_commit();
                    asm volatile("cp.async.wait_group 0;");
                    __syncwarp();
                } else {
                    const int nf = wr * NC;
                    for (int i = lane; i < nf; i += 32) sxw[i] = xb[i];
                    __syncwarp();
                }

                lse_writeback(sxw, wr);

                float f0 = 0.f, f1 = 0.f, f2 = 0.f, f3 = 0.f;
                const float* lb = lab + r0 * NC;
                if (wr == TRPW) {
                    const float4* lb4 = (const float4*)lb;
                    const float4* sxv = (const float4*)sxw;
                    float4 L0 = lb4[lane];
                    float4 L1 = lb4[lane + 32];
                    float4 L2; const bool h3 = lane < 8;
                    if (h3) L2 = lb4[lane + 64];
                    float4 X;
                    X = sxv[lane     ]; f0 += L0.x*X.x; f1 += L0.y*X.y; f2 += L0.z*X.z; f3 += L0.w*X.w;
                    X = sxv[lane + 32]; f0 += L1.x*X.x; f1 += L1.y*X.y; f2 += L1.z*X.z; f3 += L1.w*X.w;
                    if (h3) { X = sxv[lane + 64]; f0 += L2.x*X.x; f1 += L2.y*X.y; f2 += L2.z*X.z; f3 += L2.w*X.w; }
                } else {
                    const int nf = wr * NC;
                    for (int i = lane; i < nf; i += 32)
                        f0 += lb[i] * sxw[i];
                }
                acc += (double)((f0 + f1) + (f2 + f3));
                __syncwarp();
            }
        }
    }

    // ── per-warp then per-block deterministic reduction ──
    #pragma unroll
    for (int o = 16; o > 0; o >>= 1)
        acc += __shfl_down_sync(0xffffffffu, acc, o);
    if (lane == 0) sred[w] = acc;
    __syncthreads();

    if (tid == 0) {
        double v = 0.0;
        #pragma unroll
        for (int i = 0; i < NWARP; i++) v += sred[i];
        g_partials[blockIdx.x] = v;
        __threadfence();
        unsigned prev = atomicAdd(&g_count, 1u);
        s_last = (prev == gridDim.x - 1u) ? 1 : 0;
    }
    __syncthreads();

    // ── fused finalize: last block sums all partials ──
    if (s_last) {
        double v = 0.0;
        for (int i = tid; i < (int)gridDim.x; i += BLK)
            v += g_partials[i];
        #pragma unroll
        for (int o = 16; o > 0; o >>= 1)
            v += __shfl_down_sync(0xffffffffu, v, o);
        if (lane == 0) sred[w] = v;
        __syncthreads();
        if (tid == 0) {
            double t = 0.0;
            #pragma unroll
            for (int i = 0; i < NWARP; i++) t += sred[i];
            out[0] = (float)(t / (double)B);
            g_count = 0;                            // reset for next graph replay
        }
    }
}

extern "C" void kernel_launch(void* const* d_in, const int* in_sizes, int n_in,
                              void* d_out, int out_size)
{
    const float* x   = (const float*)d_in[0];   // output       [B, 18]
    const float* lab = (const float*)d_in[1];   // labels_soft  [B, 18]
    const int B = in_sizes[0] / NC;
    const int nchunks = (B + BLK - 1) / BLK;

    int grid = 148 * 4;                 // 4 blocks/SM (36 KB smem each)
    if (grid > nchunks) grid = nchunks;
    if (grid < 1) grid = 1;
    if (grid > MAX_GRID) grid = MAX_GRID;

    // Uniform main region: exact multiple of grid; remainder handled as
    // fine-grained 16-row tail slices inside the kernel.
    const int nchunks_main = (nchunks / grid) * grid;

    ce_main_kernel<<<grid, BLK>>>(x, lab, (float*)d_out, B, nchunks_main);
}